// round 16
// baseline (speedup 1.0000x reference)
#include <cuda_runtime.h>
#include <cuda_bf16.h>
#include <cstdint>
#include <math.h>

#define N_NODES  100000
#define N_EDGES  1600000
#define HIDDEN   128
#define N_GRAPHS 256
#define L1DIM    64

// ---------------- scratch (device globals; no allocations allowed) ----------
__device__ float g_pool [N_GRAPHS * HIDDEN];
__device__ float g_cnt  [N_GRAPHS];
// packed bf16x2 node features (gather table + GEMM A root half), 25.6 MB
__device__ __align__(16) unsigned g_hb  [N_NODES * 64];
// packed bf16x2 aggregation output (GEMM A rel half), 25.6 MB
__device__ __align__(16) unsigned g_aggb[N_NODES * 64];
// CSR scratch
__device__ int   g_deg     [N_NODES];
__device__ int   g_rowstart[N_NODES + 1];
__device__ int   g_cursor  [N_NODES];
__device__ int   g_bsum    [256];
__device__ int   g_boff    [256];
__device__ __align__(16) int2 g_csr[N_EDGES];
// pre-split weights: [o 0..127][k 0..255] (k<128 = rel, k>=128 = root)
__device__ __align__(16) __nv_bfloat16 g_b1hi[HIDDEN * 256];
__device__ __align__(16) __nv_bfloat16 g_b1lo[HIDDEN * 256];
__device__ __align__(16) __nv_bfloat16 g_b2hi[HIDDEN * 256];
__device__ __align__(16) __nv_bfloat16 g_b2lo[HIDDEN * 256];

// ---------------- helpers ----------------------------------------------------
__device__ __forceinline__ float warp_sum(float v) {
    #pragma unroll
    for (int m = 16; m > 0; m >>= 1) v += __shfl_xor_sync(0xffffffffu, v, m);
    return v;
}
__device__ __forceinline__ unsigned packbf(float a, float b) {
    __nv_bfloat162 t = __floats2bfloat162_rn(a, b);   // low = a (even dim)
    return *reinterpret_cast<unsigned*>(&t);
}
__device__ __forceinline__ void mma_bf16(float4& c, const unsigned* a,
                                         unsigned b0, unsigned b1) {
    asm volatile(
        "mma.sync.aligned.m16n8k16.row.col.f32.bf16.bf16.f32 "
        "{%0,%1,%2,%3}, {%4,%5,%6,%7}, {%8,%9}, {%0,%1,%2,%3};\n"
        : "+f"(c.x), "+f"(c.y), "+f"(c.z), "+f"(c.w)
        : "r"(a[0]), "r"(a[1]), "r"(a[2]), "r"(a[3]), "r"(b0), "r"(b1));
}

// ---------------- weight prep: split f32 -> bf16 hi/lo, pack [o][k] ---------
__global__ void prep_weights_kernel(const float* __restrict__ w1r,
                                    const float* __restrict__ w1o,
                                    const float* __restrict__ w2r,
                                    const float* __restrict__ w2o) {
    int i = blockIdx.x * blockDim.x + threadIdx.x;
    if (i >= HIDDEN * HIDDEN) return;
    int o = i >> 7, k = i & 127;
    float v;
    __nv_bfloat16 h;
    v = w1r[i]; h = __float2bfloat16_rn(v);
    g_b1hi[o * 256 + k] = h;
    g_b1lo[o * 256 + k] = __float2bfloat16_rn(v - __bfloat162float(h));
    v = w1o[i]; h = __float2bfloat16_rn(v);
    g_b1hi[o * 256 + 128 + k] = h;
    g_b1lo[o * 256 + 128 + k] = __float2bfloat16_rn(v - __bfloat162float(h));
    v = w2r[i]; h = __float2bfloat16_rn(v);
    g_b2hi[o * 256 + k] = h;
    g_b2lo[o * 256 + k] = __float2bfloat16_rn(v - __bfloat162float(h));
    v = w2o[i]; h = __float2bfloat16_rn(v);
    g_b2hi[o * 256 + 128 + k] = h;
    g_b2lo[o * 256 + 128 + k] = __float2bfloat16_rn(v - __bfloat162float(h));
}

// ---------------- embedding with max_norm=1 (bf16 table only) ---------------
__global__ void embed_kernel(const int* __restrict__ x,
                             const float* __restrict__ emb_w) {
    int warp = (blockIdx.x * blockDim.x + threadIdx.x) >> 5;
    int lane = threadIdx.x & 31;
    if (warp >= N_NODES) return;
    int idx = x[warp];
    const float4* row = (const float4*)(emb_w + (size_t)idx * HIDDEN);
    float4 v = __ldg(&row[lane]);
    float ss = v.x*v.x + v.y*v.y + v.z*v.z + v.w*v.w;
    ss = warp_sum(ss);
    float scale = fminf(1.0f, 1.0f / (sqrtf(ss) + 1e-7f));
    float4 o = make_float4(v.x*scale, v.y*scale, v.z*scale, v.w*scale);
    *(uint2*)(g_hb + (size_t)warp * 64 + lane * 2) =
        make_uint2(packbf(o.x, o.y), packbf(o.z, o.w));
}

// ---------------- zero kernels -----------------------------------------------
__global__ void zero_deg_kernel() {
    int i = blockIdx.x * blockDim.x + threadIdx.x;
    if (i < N_NODES) g_deg[i] = 0;
}
__global__ void zero_pool_kernel() {
    int i = threadIdx.x + blockIdx.x * blockDim.x;
    if (i < N_GRAPHS * HIDDEN) g_pool[i] = 0.f;
    if (i < N_GRAPHS) g_cnt[i] = 0.f;
}

// ---------------- CSR build ---------------------------------------------------
__global__ void hist_kernel(const int* __restrict__ eidx) {
    int e4 = blockIdx.x * blockDim.x + threadIdx.x;
    if (e4 >= N_EDGES / 4) return;
    int4 d = __ldg((const int4*)(eidx + N_EDGES) + e4);
    atomicAdd(&g_deg[d.x], 1);
    atomicAdd(&g_deg[d.y], 1);
    atomicAdd(&g_deg[d.z], 1);
    atomicAdd(&g_deg[d.w], 1);
}

#define SCCH 512
#define SCB  ((N_NODES + SCCH - 1) / SCCH)   // 196
__global__ void scanA_kernel() {
    __shared__ int s[256];
    int b = blockIdx.x, t = threadIdx.x;
    int base = b * SCCH;
    int v = 0;
    #pragma unroll
    for (int i = 0; i < 2; i++) {
        int j = base + t + i * 256;
        if (j < N_NODES) v += g_deg[j];
    }
    s[t] = v;
    __syncthreads();
    #pragma unroll
    for (int off = 128; off > 0; off >>= 1) {
        if (t < off) s[t] += s[t + off];
        __syncthreads();
    }
    if (t == 0) g_bsum[b] = s[0];
}
__global__ void scanB_kernel() {
    __shared__ int s[256];
    int t = threadIdx.x;
    int v = (t < SCB) ? g_bsum[t] : 0;
    s[t] = v;
    __syncthreads();
    #pragma unroll
    for (int off = 1; off < 256; off <<= 1) {
        int u = (t >= off) ? s[t - off] : 0;
        __syncthreads();
        s[t] += u;
        __syncthreads();
    }
    if (t < SCB) g_boff[t] = s[t] - v;            // exclusive
    if (t == 255) g_rowstart[N_NODES] = s[255];   // total
}
__global__ void scanC_kernel() {
    __shared__ int s[256];
    int b = blockIdx.x, t = threadIdx.x;
    int n0 = b * SCCH + 2 * t;
    int n1 = n0 + 1;
    int d0 = (n0 < N_NODES) ? g_deg[n0] : 0;
    int d1 = (n1 < N_NODES) ? g_deg[n1] : 0;
    int pair = d0 + d1;
    s[t] = pair;
    __syncthreads();
    #pragma unroll
    for (int off = 1; off < 256; off <<= 1) {
        int u = (t >= off) ? s[t - off] : 0;
        __syncthreads();
        s[t] += u;
        __syncthreads();
    }
    int off0 = g_boff[b] + s[t] - pair;
    if (n0 < N_NODES) { g_rowstart[n0] = off0;      g_cursor[n0] = off0; }
    if (n1 < N_NODES) { g_rowstart[n1] = off0 + d0; g_cursor[n1] = off0 + d0; }
}

__global__ void reorder_kernel(const int* __restrict__ eidx,
                               const float* __restrict__ ew) {
    int e4 = blockIdx.x * blockDim.x + threadIdx.x;
    if (e4 >= N_EDGES / 4) return;
    int4   s4 = __ldg((const int4*)eidx + e4);
    int4   d4 = __ldg((const int4*)(eidx + N_EDGES) + e4);
    float4 w4 = __ldg((const float4*)ew + e4);
    int p;
    p = atomicAdd(&g_cursor[d4.x], 1); g_csr[p] = make_int2(s4.x, __float_as_int(w4.x));
    p = atomicAdd(&g_cursor[d4.y], 1); g_csr[p] = make_int2(s4.y, __float_as_int(w4.y));
    p = atomicAdd(&g_cursor[d4.z], 1); g_csr[p] = make_int2(s4.z, __float_as_int(w4.z));
    p = atomicAdd(&g_cursor[d4.w], 1); g_csr[p] = make_int2(s4.w, __float_as_int(w4.w));
}

// ---------------- CSR aggregation: paired-edge bf16 gather -------------------
// Warp per node. Lanes split into two 16-lane halves (h = lane>>4); each half
// gathers a different edge's 256B row via LDG.128 (16 lanes x 16B). Each lane
// accumulates 8 dims; halves folded at the end via shfl_xor(16).
__device__ __forceinline__ void accum8(float2* a8, uint4 u, float w) {
    float2 f;
    f = __bfloat1622float2(*reinterpret_cast<__nv_bfloat162*>(&u.x));
    a8[0].x += f.x * w; a8[0].y += f.y * w;
    f = __bfloat1622float2(*reinterpret_cast<__nv_bfloat162*>(&u.y));
    a8[1].x += f.x * w; a8[1].y += f.y * w;
    f = __bfloat1622float2(*reinterpret_cast<__nv_bfloat162*>(&u.z));
    a8[2].x += f.x * w; a8[2].y += f.y * w;
    f = __bfloat1622float2(*reinterpret_cast<__nv_bfloat162*>(&u.w));
    a8[3].x += f.x * w; a8[3].y += f.y * w;
}

__global__ void __launch_bounds__(256)
agg_csr_kernel() {
    int warp = (blockIdx.x * blockDim.x + threadIdx.x) >> 5;
    int lane = threadIdx.x & 31;
    if (warp >= N_NODES) return;
    int h   = lane >> 4;          // half: which edge of the pair
    int sub = lane & 15;          // 16B chunk within the row (dims sub*8..+8)
    int s0 = g_rowstart[warp], s1 = g_rowstart[warp + 1];
    // lane accumulates dims [sub*8, sub*8+8) for edges of parity h
    float2 a8[4] = {{0.f,0.f},{0.f,0.f},{0.f,0.f},{0.f,0.f}};

    for (int base = s0; base < s1; base += 32) {
        int m = min(32, s1 - base);
        int2 e = make_int2(0, 0);              // lanes >= m stay (src=0, w=0)
        if (base + lane < s1) e = __ldg(&g_csr[base + lane]);

        int i = 0;
        for (; i + 7 < m; i += 8) {            // 4 pairs in flight
            int   ss[4];
            float ww[4];
            uint4 uu[4];
            #pragma unroll
            for (int p = 0; p < 4; p++) {
                int idx = i + p * 2 + h;
                ss[p] = __shfl_sync(0xffffffffu, e.x, idx);
                ww[p] = __int_as_float(__shfl_sync(0xffffffffu, e.y, idx));
            }
            #pragma unroll
            for (int p = 0; p < 4; p++)
                uu[p] = __ldg((const uint4*)(g_hb + (size_t)ss[p] * 64) + sub);
            #pragma unroll
            for (int p = 0; p < 4; p++)
                accum8(a8, uu[p], ww[p]);
        }
        for (; i < m; i += 2) {
            int idx = i + h;                   // idx<=m<=31; zero-padded e safe
            int   se = __shfl_sync(0xffffffffu, e.x, idx);
            float we = __int_as_float(__shfl_sync(0xffffffffu, e.y, idx));
            uint4 ue = __ldg((const uint4*)(g_hb + (size_t)se * 64) + sub);
            accum8(a8, ue, we);
        }
    }

    // fold the two halves (lanes l and l^16 hold partials for the same dims)
    #pragma unroll
    for (int q = 0; q < 4; q++) {
        a8[q].x += __shfl_xor_sync(0xffffffffu, a8[q].x, 16);
        a8[q].y += __shfl_xor_sync(0xffffffffu, a8[q].y, 16);
    }
    if (h == 0) {
        uint4 outp = make_uint4(packbf(a8[0].x, a8[0].y),
                                packbf(a8[1].x, a8[1].y),
                                packbf(a8[2].x, a8[2].y),
                                packbf(a8[3].x, a8[3].y));
        __stcs((uint4*)(g_aggb + (size_t)warp * 64) + sub, outp);
    }
}

// ---------------- 2-pass bf16 tensor-core dual GEMM (R13) --------------------
// out = relu([aggb | hb](100k x 256, bf16) @ (Bhi + Blo)(256 x 128) + bias)
// Block: 128 rows x 64 cols; 8 warps = 4(M) x 2(N); warp tile 32x32.
// B smem: per column, k-words permuted pos = g*8 + (i&3)*2 + (i>>2) -> LDS.64.
#define SB_COL_W      136
#define SB_PLANE_W    (64 * SB_COL_W)
#define SA_ROW_W      12
#define SA_PLANE_W    (128 * SA_ROW_W)
#define GEMM_SMEM_BYTES ((2 * SB_PLANE_W + 2 * SA_PLANE_W) * 4)   // 81920
#define OS 65

template <int FUSE_POOL>
__global__ void __launch_bounds__(256, 2)
linear_bf16_kernel(const unsigned* __restrict__ aggb,
                   const unsigned* __restrict__ hb,
                   const __nv_bfloat16* __restrict__ bhi,
                   const __nv_bfloat16* __restrict__ blo,
                   const float* __restrict__ bias,
                   unsigned* __restrict__ outB,
                   const int* __restrict__ batch) {
    extern __shared__ char smem_raw[];
    unsigned* sBhi = (unsigned*)smem_raw;
    unsigned* sBlo = sBhi + SB_PLANE_W;
    unsigned* sA   = sBlo + SB_PLANE_W;

    int tid = threadIdx.x, lane = tid & 31, warp = tid >> 5;
    int warpM = warp & 3, warpN = warp >> 2;
    int tileM = blockIdx.x >> 1;
    int nb = (blockIdx.x & 1) * 64;
    int rowBase = tileM * 128;

    const uint4* srcHi = (const uint4*)(bhi + (size_t)nb * 256);
    const uint4* srcLo = (const uint4*)(blo + (size_t)nb * 256);
    #pragma unroll
    for (int it = 0; it < 8; it++) {
        int idx = it * 256 + tid;
        int col = idx >> 5, q = idx & 31;
        uint4 v = __ldg(srcHi + col * 32 + q);
        uint4 w = __ldg(srcLo + col * 32 + q);
        unsigned* dh = sBhi + col * SB_COL_W;
        unsigned* dl = sBlo + col * SB_COL_W;
        int W = q * 4;
        #pragma unroll
        for (int u = 0; u < 4; u++) {
            int Wk = W + u;
            int pos = (Wk & ~7) + ((Wk & 3) << 1) + ((Wk >> 2) & 1);
            unsigned hv = (u == 0) ? v.x : (u == 1) ? v.y : (u == 2) ? v.z : v.w;
            unsigned lv = (u == 0) ? w.x : (u == 1) ? w.y : (u == 2) ? w.z : w.w;
            dh[pos] = hv;
            dl[pos] = lv;
        }
    }

    int rA = tid >> 1, qA = tid & 1;
    uint4 cur, pre;
    auto loadA = [&](int s, uint4& dst) {
        const unsigned* src = (s < 8) ? aggb : hb;
        int woff = (s & 7) * 8 + qA * 4;
        int node = rowBase + rA;
        dst = make_uint4(0u, 0u, 0u, 0u);
        if (node < N_NODES)
            dst = __ldg((const uint4*)(src + (size_t)node * 64 + woff));
    };
    auto storeA = [&](int buf, const uint4& v) {
        *(uint4*)(sA + buf * SA_PLANE_W + rA * SA_ROW_W + qA * 4) = v;
    };

    loadA(0, cur);
    storeA(0, cur);
    __syncthreads();

    float4 acc[2][4];
    #pragma unroll
    for (int mt = 0; mt < 2; mt++)
        #pragma unroll
        for (int j = 0; j < 4; j++)
            acc[mt][j] = make_float4(0.f, 0.f, 0.f, 0.f);

    for (int s = 0; s < 16; s++) {
        if (s < 15) loadA(s + 1, pre);

        const unsigned* Ab = sA + (s & 1) * SA_PLANE_W;

        unsigned ah[2][4];
        #pragma unroll
        for (int mt = 0; mt < 2; mt++) {
            int r0 = warpM * 32 + mt * 16 + (lane >> 2);
            int w0 = lane & 3;
            ah[mt][0] = Ab[r0 * SA_ROW_W + w0];
            ah[mt][1] = Ab[(r0 + 8) * SA_ROW_W + w0];
            ah[mt][2] = Ab[r0 * SA_ROW_W + w0 + 4];
            ah[mt][3] = Ab[(r0 + 8) * SA_ROW_W + w0 + 4];
        }
        uint2 bh[4], bl[4];
        #pragma unroll
        for (int j = 0; j < 4; j++) {
            int c = warpN * 32 + j * 8 + (lane >> 2);
            int w = c * SB_COL_W + s * 8 + (lane & 3) * 2;
            bh[j] = *(const uint2*)(sBhi + w);
            bl[j] = *(const uint2*)(sBlo + w);
        }
        #pragma unroll
        for (int mt = 0; mt < 2; mt++)
            #pragma unroll
            for (int j = 0; j < 4; j++) {
                mma_bf16(acc[mt][j], ah[mt], bh[j].x, bh[j].y);
                mma_bf16(acc[mt][j], ah[mt], bl[j].x, bl[j].y);
            }

        if (s < 15) storeA((s + 1) & 1, pre);
        __syncthreads();
    }

    if (FUSE_POOL == 0) {
        #pragma unroll
        for (int mt = 0; mt < 2; mt++) {
            #pragma unroll
            for (int j = 0; j < 4; j++) {
                int col = nb + warpN * 32 + j * 8 + (lane & 3) * 2;
                float b0 = __ldg(bias + col);
                float b1 = __ldg(bias + col + 1);
                int row0 = rowBase + warpM * 32 + mt * 16 + (lane >> 2);
                int row1 = row0 + 8;
                float4 c = acc[mt][j];
                if (row0 < N_NODES)
                    outB[(size_t)row0 * 64 + (col >> 1)] =
                        packbf(fmaxf(c.x + b0, 0.f), fmaxf(c.y + b1, 0.f));
                if (row1 < N_NODES)
                    outB[(size_t)row1 * 64 + (col >> 1)] =
                        packbf(fmaxf(c.z + b0, 0.f), fmaxf(c.w + b1, 0.f));
            }
        }
    } else {
        float* sOut = (float*)smem_raw;
        #pragma unroll
        for (int mt = 0; mt < 2; mt++) {
            #pragma unroll
            for (int j = 0; j < 4; j++) {
                int colL = warpN * 32 + j * 8 + (lane & 3) * 2;
                float b0 = __ldg(bias + nb + colL);
                float b1 = __ldg(bias + nb + colL + 1);
                int r0L = warpM * 32 + mt * 16 + (lane >> 2);
                int r1L = r0L + 8;
                float4 c = acc[mt][j];
                sOut[r0L * OS + colL]     = fmaxf(c.x + b0, 0.f);
                sOut[r0L * OS + colL + 1] = fmaxf(c.y + b1, 0.f);
                sOut[r1L * OS + colL]     = fmaxf(c.z + b0, 0.f);
                sOut[r1L * OS + colL + 1] = fmaxf(c.w + b1, 0.f);
            }
        }
        __syncthreads();

        int c = tid & 63;
        int q = tid >> 6;
        float accp = 0.f, cnt = 0.f;
        int curg = -1;
        for (int r = 0; r < 32; r++) {
            int rL = q * 32 + r;
            int node = rowBase + rL;
            if (node >= N_NODES) break;
            int b = __ldg(batch + node);
            if (b != curg) {
                if (curg >= 0) {
                    atomicAdd(&g_pool[curg * HIDDEN + nb + c], accp);
                    if (c == 0 && nb == 0) atomicAdd(&g_cnt[curg], cnt);
                }
                accp = 0.f; cnt = 0.f; curg = b;
            }
            accp += sOut[rL * OS + c];
            cnt += 1.f;
        }
        if (curg >= 0) {
            atomicAdd(&g_pool[curg * HIDDEN + nb + c], accp);
            if (c == 0 && nb == 0) atomicAdd(&g_cnt[curg], cnt);
        }
    }
}

// ---------------- classifier -------------------------------------------------
__global__ void __launch_bounds__(256)
classifier_kernel(const float* __restrict__ cls1_w,
                  const float* __restrict__ cls1_b,
                  const float* __restrict__ cls2_w,
                  const float* __restrict__ cls2_b,
                  float* __restrict__ out) {
    __shared__ float s_w1[L1DIM * HIDDEN];
    __shared__ float s_b1[L1DIM];
    __shared__ float s_w2[2 * L1DIM];
    __shared__ float s_b2[2];

    for (int i = threadIdx.x; i < L1DIM * HIDDEN; i += blockDim.x)
        s_w1[i] = cls1_w[i];
    if (threadIdx.x < L1DIM) s_b1[threadIdx.x] = cls1_b[threadIdx.x];
    if (threadIdx.x < 2 * L1DIM) s_w2[threadIdx.x] = cls2_w[threadIdx.x];
    if (threadIdx.x < 2) s_b2[threadIdx.x] = cls2_b[threadIdx.x];
    __syncthreads();

    int g = blockIdx.x * 8 + (threadIdx.x >> 5);
    int lane = threadIdx.x & 31;
    if (g >= N_GRAPHS) return;

    float c = fmaxf(g_cnt[g], 1.0f);
    float4 p = ((const float4*)(g_pool + g * HIDDEN))[lane];
    float inv = 1.0f / c;
    p.x *= inv; p.y *= inv; p.z *= inv; p.w *= inv;

    float z1a = 0.f, z1b = 0.f;
    const float4* w14 = (const float4*)s_w1;
    #pragma unroll 4
    for (int j = 0; j < L1DIM; j++) {
        float4 w = w14[j * 32 + lane];
        float s = p.x*w.x + p.y*w.y + p.z*w.z + p.w*w.w;
        s = warp_sum(s);
        float v = fmaxf(s + s_b1[j], 0.f);
        if (j < 32) { if (lane == j)      z1a = v; }
        else        { if (lane == j - 32) z1b = v; }
    }
    float t0 = s_w2[lane] * z1a + s_w2[lane + 32] * z1b;
    float t1 = s_w2[L1DIM + lane] * z1a + s_w2[L1DIM + lane + 32] * z1b;
    t0 = warp_sum(t0);
    t1 = warp_sum(t1);
    if (lane == 0) {
        float z0 = t0 + s_b2[0];
        float z1 = t1 + s_b2[1];
        float m = fmaxf(z0, z1);
        float e0 = expf(z0 - m), e1 = expf(z1 - m);
        float d = e0 + e1;
        out[g * 2 + 0] = e0 / d;
        out[g * 2 + 1] = e1 / d;
    }
}

// ---------------- launch ----------------------------------------------------
extern "C" void kernel_launch(void* const* d_in, const int* in_sizes, int n_in,
                              void* d_out, int out_size) {
    const int*   x       = (const int*)  d_in[0];
    const int*   eidx    = (const int*)  d_in[1];
    const float* eweight = (const float*)d_in[2];
    const int*   batch   = (const int*)  d_in[3];
    const float* emb_w   = (const float*)d_in[4];
    const float* w1_rel  = (const float*)d_in[5];
    const float* b1_rel  = (const float*)d_in[6];
    const float* w1_root = (const float*)d_in[7];
    const float* w2_rel  = (const float*)d_in[8];
    const float* b2_rel  = (const float*)d_in[9];
    const float* w2_root = (const float*)d_in[10];
    const float* cls1_w  = (const float*)d_in[11];
    const float* cls1_b  = (const float*)d_in[12];
    const float* cls2_w  = (const float*)d_in[13];
    const float* cls2_b  = (const float*)d_in[14];
    float* out = (float*)d_out;

    unsigned *p_hb, *p_aggb;
    __nv_bfloat16 *p_b1hi, *p_b1lo, *p_b2hi, *p_b2lo;
    cudaGetSymbolAddress((void**)&p_hb,   g_hb);
    cudaGetSymbolAddress((void**)&p_aggb, g_aggb);
    cudaGetSymbolAddress((void**)&p_b1hi, g_b1hi);
    cudaGetSymbolAddress((void**)&p_b1lo, g_b1lo);
    cudaGetSymbolAddress((void**)&p_b2hi, g_b2hi);
    cudaGetSymbolAddress((void**)&p_b2lo, g_b2lo);

    static cudaStream_t s2 = nullptr;
    static cudaEvent_t evFork = nullptr, evJoin = nullptr;
    static int smem_set = 0;
    if (!smem_set) {
        cudaFuncSetAttribute(linear_bf16_kernel<0>,
                             cudaFuncAttributeMaxDynamicSharedMemorySize,
                             GEMM_SMEM_BYTES);
        cudaFuncSetAttribute(linear_bf16_kernel<1>,
                             cudaFuncAttributeMaxDynamicSharedMemorySize,
                             GEMM_SMEM_BYTES);
        cudaStreamCreateWithFlags(&s2, cudaStreamNonBlocking);
        cudaEventCreateWithFlags(&evFork, cudaEventDisableTiming);
        cudaEventCreateWithFlags(&evJoin, cudaEventDisableTiming);
        smem_set = 1;
    }

    // ---- fork: CSR build on side stream, embedding path on main stream ----
    cudaEventRecord(evFork, 0);
    cudaStreamWaitEvent(s2, evFork, 0);

    zero_deg_kernel<<<(N_NODES + 255) / 256, 256, 0, s2>>>();
    hist_kernel<<<(N_EDGES / 4 + 255) / 256, 256, 0, s2>>>(eidx);
    scanA_kernel<<<SCB, 256, 0, s2>>>();
    scanB_kernel<<<1, 256, 0, s2>>>();
    scanC_kernel<<<SCB, 256, 0, s2>>>();
    reorder_kernel<<<(N_EDGES / 4 + 255) / 256, 256, 0, s2>>>(eidx, eweight);
    cudaEventRecord(evJoin, s2);

    prep_weights_kernel<<<64, 256>>>(w1_rel, w1_root, w2_rel, w2_root);
    zero_pool_kernel<<<(N_GRAPHS * HIDDEN + 255) / 256, 256>>>();
    embed_kernel<<<(N_NODES + 7) / 8, 256>>>(x, emb_w);

    cudaStreamWaitEvent(0, evJoin, 0);

    int nTiles = (N_NODES + 127) / 128;
    // layer 1: out -> g_hb (bf16)
    agg_csr_kernel<<<(N_NODES * 32 + 255) / 256, 256>>>();
    linear_bf16_kernel<0><<<nTiles * 2, 256, GEMM_SMEM_BYTES>>>(
        p_aggb, p_hb, p_b1hi, p_b1lo, b1_rel, p_hb, nullptr);
    // layer 2: fused fp32 pooling
    agg_csr_kernel<<<(N_NODES * 32 + 255) / 256, 256>>>();
    linear_bf16_kernel<1><<<nTiles * 2, 256, GEMM_SMEM_BYTES>>>(
        p_aggb, p_hb, p_b2hi, p_b2lo, b2_rel, nullptr, batch);

    classifier_kernel<<<32, 256>>>(cls1_w, cls1_b, cls2_w, cls2_b, out);
}

// round 17
// speedup vs baseline: 1.0715x; 1.0715x over previous
#include <cuda_runtime.h>
#include <cuda_bf16.h>
#include <cstdint>
#include <math.h>

#define N_NODES  100000
#define N_EDGES  1600000
#define HIDDEN   128
#define N_GRAPHS 256
#define L1DIM    64

// ---------------- scratch (device globals; no allocations allowed) ----------
__device__ float g_pool [N_GRAPHS * HIDDEN];
__device__ float g_cnt  [N_GRAPHS];
// packed bf16x2 node features (gather table + GEMM A root half), 25.6 MB
__device__ __align__(16) unsigned g_hb  [N_NODES * 64];
// packed bf16x2 aggregation output (GEMM A rel half), 25.6 MB
__device__ __align__(16) unsigned g_aggb[N_NODES * 64];
// CSR scratch
__device__ int   g_deg     [N_NODES];
__device__ int   g_rowstart[N_NODES + 1];
__device__ int   g_cursor  [N_NODES];
__device__ int   g_bsum    [256];
__device__ int   g_boff    [256];
__device__ __align__(16) int2 g_csr[N_EDGES];
// pre-split weights: [o 0..127][k 0..255] (k<128 = rel, k>=128 = root)
__device__ __align__(16) __nv_bfloat16 g_b1hi[HIDDEN * 256];
__device__ __align__(16) __nv_bfloat16 g_b1lo[HIDDEN * 256];
__device__ __align__(16) __nv_bfloat16 g_b2hi[HIDDEN * 256];
__device__ __align__(16) __nv_bfloat16 g_b2lo[HIDDEN * 256];

// ---------------- helpers ----------------------------------------------------
__device__ __forceinline__ float warp_sum(float v) {
    #pragma unroll
    for (int m = 16; m > 0; m >>= 1) v += __shfl_xor_sync(0xffffffffu, v, m);
    return v;
}
__device__ __forceinline__ unsigned packbf(float a, float b) {
    __nv_bfloat162 t = __floats2bfloat162_rn(a, b);   // low = a (even dim)
    return *reinterpret_cast<unsigned*>(&t);
}
__device__ __forceinline__ void accum_bf(float4& acc, uint2 u, float w) {
    float2 f0 = __bfloat1622float2(*reinterpret_cast<__nv_bfloat162*>(&u.x));
    float2 f1 = __bfloat1622float2(*reinterpret_cast<__nv_bfloat162*>(&u.y));
    acc.x += f0.x * w;
    acc.y += f0.y * w;
    acc.z += f1.x * w;
    acc.w += f1.y * w;
}
__device__ __forceinline__ void mma_bf16(float4& c, const unsigned* a,
                                         unsigned b0, unsigned b1) {
    asm volatile(
        "mma.sync.aligned.m16n8k16.row.col.f32.bf16.bf16.f32 "
        "{%0,%1,%2,%3}, {%4,%5,%6,%7}, {%8,%9}, {%0,%1,%2,%3};\n"
        : "+f"(c.x), "+f"(c.y), "+f"(c.z), "+f"(c.w)
        : "r"(a[0]), "r"(a[1]), "r"(a[2]), "r"(a[3]), "r"(b0), "r"(b1));
}

// ---------------- weight prep: split f32 -> bf16 hi/lo, pack [o][k] ---------
__global__ void prep_weights_kernel(const float* __restrict__ w1r,
                                    const float* __restrict__ w1o,
                                    const float* __restrict__ w2r,
                                    const float* __restrict__ w2o) {
    int i = blockIdx.x * blockDim.x + threadIdx.x;
    if (i >= HIDDEN * HIDDEN) return;
    int o = i >> 7, k = i & 127;
    float v;
    __nv_bfloat16 h;
    v = w1r[i]; h = __float2bfloat16_rn(v);
    g_b1hi[o * 256 + k] = h;
    g_b1lo[o * 256 + k] = __float2bfloat16_rn(v - __bfloat162float(h));
    v = w1o[i]; h = __float2bfloat16_rn(v);
    g_b1hi[o * 256 + 128 + k] = h;
    g_b1lo[o * 256 + 128 + k] = __float2bfloat16_rn(v - __bfloat162float(h));
    v = w2r[i]; h = __float2bfloat16_rn(v);
    g_b2hi[o * 256 + k] = h;
    g_b2lo[o * 256 + k] = __float2bfloat16_rn(v - __bfloat162float(h));
    v = w2o[i]; h = __float2bfloat16_rn(v);
    g_b2hi[o * 256 + 128 + k] = h;
    g_b2lo[o * 256 + 128 + k] = __float2bfloat16_rn(v - __bfloat162float(h));
}

// ---------------- embedding with max_norm=1 (bf16 table only) ---------------
__global__ void embed_kernel(const int* __restrict__ x,
                             const float* __restrict__ emb_w) {
    int warp = (blockIdx.x * blockDim.x + threadIdx.x) >> 5;
    int lane = threadIdx.x & 31;
    if (warp >= N_NODES) return;
    int idx = x[warp];
    const float4* row = (const float4*)(emb_w + (size_t)idx * HIDDEN);
    float4 v = __ldg(&row[lane]);
    float ss = v.x*v.x + v.y*v.y + v.z*v.z + v.w*v.w;
    ss = warp_sum(ss);
    float scale = fminf(1.0f, 1.0f / (sqrtf(ss) + 1e-7f));
    float4 o = make_float4(v.x*scale, v.y*scale, v.z*scale, v.w*scale);
    *(uint2*)(g_hb + (size_t)warp * 64 + lane * 2) =
        make_uint2(packbf(o.x, o.y), packbf(o.z, o.w));
}

// ---------------- zero kernels -----------------------------------------------
__global__ void zero_deg_kernel() {
    int i = blockIdx.x * blockDim.x + threadIdx.x;
    if (i < N_NODES) g_deg[i] = 0;
}
__global__ void zero_pool_kernel() {
    int i = threadIdx.x + blockIdx.x * blockDim.x;
    if (i < N_GRAPHS * HIDDEN) g_pool[i] = 0.f;
    if (i < N_GRAPHS) g_cnt[i] = 0.f;
}

// ---------------- CSR build ---------------------------------------------------
__global__ void hist_kernel(const int* __restrict__ eidx) {
    int e4 = blockIdx.x * blockDim.x + threadIdx.x;
    if (e4 >= N_EDGES / 4) return;
    int4 d = __ldg((const int4*)(eidx + N_EDGES) + e4);
    atomicAdd(&g_deg[d.x], 1);
    atomicAdd(&g_deg[d.y], 1);
    atomicAdd(&g_deg[d.z], 1);
    atomicAdd(&g_deg[d.w], 1);
}

#define SCCH 512
#define SCB  ((N_NODES + SCCH - 1) / SCCH)   // 196
__global__ void scanA_kernel() {
    __shared__ int s[256];
    int b = blockIdx.x, t = threadIdx.x;
    int base = b * SCCH;
    int v = 0;
    #pragma unroll
    for (int i = 0; i < 2; i++) {
        int j = base + t + i * 256;
        if (j < N_NODES) v += g_deg[j];
    }
    s[t] = v;
    __syncthreads();
    #pragma unroll
    for (int off = 128; off > 0; off >>= 1) {
        if (t < off) s[t] += s[t + off];
        __syncthreads();
    }
    if (t == 0) g_bsum[b] = s[0];
}
__global__ void scanB_kernel() {
    __shared__ int s[256];
    int t = threadIdx.x;
    int v = (t < SCB) ? g_bsum[t] : 0;
    s[t] = v;
    __syncthreads();
    #pragma unroll
    for (int off = 1; off < 256; off <<= 1) {
        int u = (t >= off) ? s[t - off] : 0;
        __syncthreads();
        s[t] += u;
        __syncthreads();
    }
    if (t < SCB) g_boff[t] = s[t] - v;            // exclusive
    if (t == 255) g_rowstart[N_NODES] = s[255];   // total
}
__global__ void scanC_kernel() {
    __shared__ int s[256];
    int b = blockIdx.x, t = threadIdx.x;
    int n0 = b * SCCH + 2 * t;
    int n1 = n0 + 1;
    int d0 = (n0 < N_NODES) ? g_deg[n0] : 0;
    int d1 = (n1 < N_NODES) ? g_deg[n1] : 0;
    int pair = d0 + d1;
    s[t] = pair;
    __syncthreads();
    #pragma unroll
    for (int off = 1; off < 256; off <<= 1) {
        int u = (t >= off) ? s[t - off] : 0;
        __syncthreads();
        s[t] += u;
        __syncthreads();
    }
    int off0 = g_boff[b] + s[t] - pair;
    if (n0 < N_NODES) { g_rowstart[n0] = off0;      g_cursor[n0] = off0; }
    if (n1 < N_NODES) { g_rowstart[n1] = off0 + d0; g_cursor[n1] = off0 + d0; }
}

__global__ void reorder_kernel(const int* __restrict__ eidx,
                               const float* __restrict__ ew) {
    int e4 = blockIdx.x * blockDim.x + threadIdx.x;
    if (e4 >= N_EDGES / 4) return;
    int4   s4 = __ldg((const int4*)eidx + e4);
    int4   d4 = __ldg((const int4*)(eidx + N_EDGES) + e4);
    float4 w4 = __ldg((const float4*)ew + e4);
    int p;
    p = atomicAdd(&g_cursor[d4.x], 1); g_csr[p] = make_int2(s4.x, __float_as_int(w4.x));
    p = atomicAdd(&g_cursor[d4.y], 1); g_csr[p] = make_int2(s4.y, __float_as_int(w4.y));
    p = atomicAdd(&g_cursor[d4.z], 1); g_csr[p] = make_int2(s4.z, __float_as_int(w4.z));
    p = atomicAdd(&g_cursor[d4.w], 1); g_csr[p] = make_int2(s4.w, __float_as_int(w4.w));
}

// ---------------- CSR aggregation, bf16 gather, warp per node, MLP 4 --------
__global__ void __launch_bounds__(256)
agg_csr_kernel() {
    int warp = (blockIdx.x * blockDim.x + threadIdx.x) >> 5;
    int lane = threadIdx.x & 31;
    if (warp >= N_NODES) return;
    int s0 = g_rowstart[warp], s1 = g_rowstart[warp + 1];
    float4 acc = make_float4(0.f, 0.f, 0.f, 0.f);

    for (int base = s0; base < s1; base += 32) {
        int m = min(32, s1 - base);
        int2 e = make_int2(0, 0);
        if (base + lane < s1) e = __ldg(&g_csr[base + lane]);

        int i = 0;
        for (; i + 3 < m; i += 4) {
            int   sA = __shfl_sync(0xffffffffu, e.x, i);
            float wA = __int_as_float(__shfl_sync(0xffffffffu, e.y, i));
            int   sB = __shfl_sync(0xffffffffu, e.x, i + 1);
            float wB = __int_as_float(__shfl_sync(0xffffffffu, e.y, i + 1));
            int   sC = __shfl_sync(0xffffffffu, e.x, i + 2);
            float wC = __int_as_float(__shfl_sync(0xffffffffu, e.y, i + 2));
            int   sD = __shfl_sync(0xffffffffu, e.x, i + 3);
            float wD = __int_as_float(__shfl_sync(0xffffffffu, e.y, i + 3));
            uint2 uA = __ldg((const uint2*)(g_hb + (size_t)sA * 64) + lane);
            uint2 uB = __ldg((const uint2*)(g_hb + (size_t)sB * 64) + lane);
            uint2 uC = __ldg((const uint2*)(g_hb + (size_t)sC * 64) + lane);
            uint2 uD = __ldg((const uint2*)(g_hb + (size_t)sD * 64) + lane);
            accum_bf(acc, uA, wA);
            accum_bf(acc, uB, wB);
            accum_bf(acc, uC, wC);
            accum_bf(acc, uD, wD);
        }
        for (; i < m; i++) {
            int   se = __shfl_sync(0xffffffffu, e.x, i);
            float we = __int_as_float(__shfl_sync(0xffffffffu, e.y, i));
            uint2 ue = __ldg((const uint2*)(g_hb + (size_t)se * 64) + lane);
            accum_bf(acc, ue, we);
        }
    }
    uint2 outp = make_uint2(packbf(acc.x, acc.y), packbf(acc.z, acc.w));
    __stcs((uint2*)(g_aggb + (size_t)warp * 64) + lane, outp);
}

// ---------------- 2-pass bf16 tensor-core dual GEMM --------------------------
// out = relu([aggb | hb](100k x 256, bf16) @ (Bhi + Blo)(256 x 128) + bias)
// Block: 128 rows x 64 cols; 8 warps = 4(M) x 2(N); warp tile 32x32.
// B smem: per column, k-words permuted pos = g*8 + (i&3)*2 + (i>>2) -> LDS.64.
// A double-buffered in 2-STAGE GROUPS (4 planes) -> one barrier per 32 k.
#define SB_COL_W      136
#define SB_PLANE_W    (64 * SB_COL_W)
#define SA_ROW_W      12
#define SA_PLANE_W    (128 * SA_ROW_W)
#define GEMM_SMEM_BYTES ((2 * SB_PLANE_W + 4 * SA_PLANE_W) * 4)   // 94208
#define OS 65

template <int FUSE_POOL>
__global__ void __launch_bounds__(256, 2)
linear_bf16_kernel(const unsigned* __restrict__ aggb,
                   const unsigned* __restrict__ hb,
                   const __nv_bfloat16* __restrict__ bhi,
                   const __nv_bfloat16* __restrict__ blo,
                   const float* __restrict__ bias,
                   unsigned* __restrict__ outB,
                   const int* __restrict__ batch) {
    extern __shared__ char smem_raw[];
    unsigned* sBhi = (unsigned*)smem_raw;
    unsigned* sBlo = sBhi + SB_PLANE_W;
    unsigned* sA   = sBlo + SB_PLANE_W;

    int tid = threadIdx.x, lane = tid & 31, warp = tid >> 5;
    int warpM = warp & 3, warpN = warp >> 2;
    int tileM = blockIdx.x >> 1;
    int nb = (blockIdx.x & 1) * 64;
    int rowBase = tileM * 128;

    const uint4* srcHi = (const uint4*)(bhi + (size_t)nb * 256);
    const uint4* srcLo = (const uint4*)(blo + (size_t)nb * 256);
    #pragma unroll
    for (int it = 0; it < 8; it++) {
        int idx = it * 256 + tid;
        int col = idx >> 5, q = idx & 31;
        uint4 v = __ldg(srcHi + col * 32 + q);
        uint4 w = __ldg(srcLo + col * 32 + q);
        unsigned* dh = sBhi + col * SB_COL_W;
        unsigned* dl = sBlo + col * SB_COL_W;
        int W = q * 4;
        #pragma unroll
        for (int u = 0; u < 4; u++) {
            int Wk = W + u;
            int pos = (Wk & ~7) + ((Wk & 3) << 1) + ((Wk >> 2) & 1);
            unsigned hv = (u == 0) ? v.x : (u == 1) ? v.y : (u == 2) ? v.z : v.w;
            unsigned lv = (u == 0) ? w.x : (u == 1) ? w.y : (u == 2) ? w.z : w.w;
            dh[pos] = hv;
            dl[pos] = lv;
        }
    }

    // ---- A loader: GROUP g covers stages 2g, 2g+1 (k = g*32 .. g*32+31) ----
    int rA = tid >> 1, qA = tid & 1;
    uint4 cur[2], pre[2];
    auto loadA2 = [&](int g, uint4* dst) {
        int node = rowBase + rA;
        #pragma unroll
        for (int sub = 0; sub < 2; sub++) {
            int s = g * 2 + sub;
            const unsigned* src = (s < 8) ? aggb : hb;
            int woff = (s & 7) * 8 + qA * 4;
            dst[sub] = make_uint4(0u, 0u, 0u, 0u);
            if (node < N_NODES)
                dst[sub] = __ldg((const uint4*)(src + (size_t)node * 64 + woff));
        }
    };
    auto storeA2 = [&](int buf, const uint4* v) {
        #pragma unroll
        for (int sub = 0; sub < 2; sub++)
            *(uint4*)(sA + (buf * 2 + sub) * SA_PLANE_W + rA * SA_ROW_W + qA * 4)
                = v[sub];
    };

    loadA2(0, cur);
    storeA2(0, cur);
    __syncthreads();

    float4 acc[2][4];
    #pragma unroll
    for (int mt = 0; mt < 2; mt++)
        #pragma unroll
        for (int j = 0; j < 4; j++)
            acc[mt][j] = make_float4(0.f, 0.f, 0.f, 0.f);

    for (int g = 0; g < 8; g++) {
        if (g < 7) loadA2(g + 1, pre);

        #pragma unroll
        for (int sub = 0; sub < 2; sub++) {
            int s = g * 2 + sub;
            const unsigned* Ab = sA + ((g & 1) * 2 + sub) * SA_PLANE_W;

            unsigned ah[2][4];
            #pragma unroll
            for (int mt = 0; mt < 2; mt++) {
                int r0 = warpM * 32 + mt * 16 + (lane >> 2);
                int w0 = lane & 3;
                ah[mt][0] = Ab[r0 * SA_ROW_W + w0];
                ah[mt][1] = Ab[(r0 + 8) * SA_ROW_W + w0];
                ah[mt][2] = Ab[r0 * SA_ROW_W + w0 + 4];
                ah[mt][3] = Ab[(r0 + 8) * SA_ROW_W + w0 + 4];
            }
            uint2 bh[4], bl[4];
            #pragma unroll
            for (int j = 0; j < 4; j++) {
                int c = warpN * 32 + j * 8 + (lane >> 2);
                int w = c * SB_COL_W + s * 8 + (lane & 3) * 2;
                bh[j] = *(const uint2*)(sBhi + w);
                bl[j] = *(const uint2*)(sBlo + w);
            }
            #pragma unroll
            for (int mt = 0; mt < 2; mt++)
                #pragma unroll
                for (int j = 0; j < 4; j++) {
                    mma_bf16(acc[mt][j], ah[mt], bh[j].x, bh[j].y);
                    mma_bf16(acc[mt][j], ah[mt], bl[j].x, bl[j].y);
                }
        }

        if (g < 7) storeA2((g + 1) & 1, pre);
        __syncthreads();
    }

    if (FUSE_POOL == 0) {
        #pragma unroll
        for (int mt = 0; mt < 2; mt++) {
            #pragma unroll
            for (int j = 0; j < 4; j++) {
                int col = nb + warpN * 32 + j * 8 + (lane & 3) * 2;
                float b0 = __ldg(bias + col);
                float b1 = __ldg(bias + col + 1);
                int row0 = rowBase + warpM * 32 + mt * 16 + (lane >> 2);
                int row1 = row0 + 8;
                float4 c = acc[mt][j];
                if (row0 < N_NODES)
                    outB[(size_t)row0 * 64 + (col >> 1)] =
                        packbf(fmaxf(c.x + b0, 0.f), fmaxf(c.y + b1, 0.f));
                if (row1 < N_NODES)
                    outB[(size_t)row1 * 64 + (col >> 1)] =
                        packbf(fmaxf(c.z + b0, 0.f), fmaxf(c.w + b1, 0.f));
            }
        }
    } else {
        float* sOut = (float*)smem_raw;
        #pragma unroll
        for (int mt = 0; mt < 2; mt++) {
            #pragma unroll
            for (int j = 0; j < 4; j++) {
                int colL = warpN * 32 + j * 8 + (lane & 3) * 2;
                float b0 = __ldg(bias + nb + colL);
                float b1 = __ldg(bias + nb + colL + 1);
                int r0L = warpM * 32 + mt * 16 + (lane >> 2);
                int r1L = r0L + 8;
                float4 c = acc[mt][j];
                sOut[r0L * OS + colL]     = fmaxf(c.x + b0, 0.f);
                sOut[r0L * OS + colL + 1] = fmaxf(c.y + b1, 0.f);
                sOut[r1L * OS + colL]     = fmaxf(c.z + b0, 0.f);
                sOut[r1L * OS + colL + 1] = fmaxf(c.w + b1, 0.f);
            }
        }
        __syncthreads();

        int c = tid & 63;
        int q = tid >> 6;
        float accp = 0.f, cnt = 0.f;
        int curg = -1;
        for (int r = 0; r < 32; r++) {
            int rL = q * 32 + r;
            int node = rowBase + rL;
            if (node >= N_NODES) break;
            int b = __ldg(batch + node);
            if (b != curg) {
                if (curg >= 0) {
                    atomicAdd(&g_pool[curg * HIDDEN + nb + c], accp);
                    if (c == 0 && nb == 0) atomicAdd(&g_cnt[curg], cnt);
                }
                accp = 0.f; cnt = 0.f; curg = b;
            }
            accp += sOut[rL * OS + c];
            cnt += 1.f;
        }
        if (curg >= 0) {
            atomicAdd(&g_pool[curg * HIDDEN + nb + c], accp);
            if (c == 0 && nb == 0) atomicAdd(&g_cnt[curg], cnt);
        }
    }
}

// ---------------- classifier -------------------------------------------------
__global__ void __launch_bounds__(256)
classifier_kernel(const float* __restrict__ cls1_w,
                  const float* __restrict__ cls1_b,
                  const float* __restrict__ cls2_w,
                  const float* __restrict__ cls2_b,
                  float* __restrict__ out) {
    __shared__ float s_w1[L1DIM * HIDDEN];
    __shared__ float s_b1[L1DIM];
    __shared__ float s_w2[2 * L1DIM];
    __shared__ float s_b2[2];

    for (int i = threadIdx.x; i < L1DIM * HIDDEN; i += blockDim.x)
        s_w1[i] = cls1_w[i];
    if (threadIdx.x < L1DIM) s_b1[threadIdx.x] = cls1_b[threadIdx.x];
    if (threadIdx.x < 2 * L1DIM) s_w2[threadIdx.x] = cls2_w[threadIdx.x];
    if (threadIdx.x < 2) s_b2[threadIdx.x] = cls2_b[threadIdx.x];
    __syncthreads();

    int g = blockIdx.x * 8 + (threadIdx.x >> 5);
    int lane = threadIdx.x & 31;
    if (g >= N_GRAPHS) return;

    float c = fmaxf(g_cnt[g], 1.0f);
    float4 p = ((const float4*)(g_pool + g * HIDDEN))[lane];
    float inv = 1.0f / c;
    p.x *= inv; p.y *= inv; p.z *= inv; p.w *= inv;

    float z1a = 0.f, z1b = 0.f;
    const float4* w14 = (const float4*)s_w1;
    #pragma unroll 4
    for (int j = 0; j < L1DIM; j++) {
        float4 w = w14[j * 32 + lane];
        float s = p.x*w.x + p.y*w.y + p.z*w.z + p.w*w.w;
        s = warp_sum(s);
        float v = fmaxf(s + s_b1[j], 0.f);
        if (j < 32) { if (lane == j)      z1a = v; }
        else        { if (lane == j - 32) z1b = v; }
    }
    float t0 = s_w2[lane] * z1a + s_w2[lane + 32] * z1b;
    float t1 = s_w2[L1DIM + lane] * z1a + s_w2[L1DIM + lane + 32] * z1b;
    t0 = warp_sum(t0);
    t1 = warp_sum(t1);
    if (lane == 0) {
        float z0 = t0 + s_b2[0];
        float z1 = t1 + s_b2[1];
        float m = fmaxf(z0, z1);
        float e0 = expf(z0 - m), e1 = expf(z1 - m);
        float d = e0 + e1;
        out[g * 2 + 0] = e0 / d;
        out[g * 2 + 1] = e1 / d;
    }
}

// ---------------- launch ----------------------------------------------------
extern "C" void kernel_launch(void* const* d_in, const int* in_sizes, int n_in,
                              void* d_out, int out_size) {
    const int*   x       = (const int*)  d_in[0];
    const int*   eidx    = (const int*)  d_in[1];
    const float* eweight = (const float*)d_in[2];
    const int*   batch   = (const int*)  d_in[3];
    const float* emb_w   = (const float*)d_in[4];
    const float* w1_rel  = (const float*)d_in[5];
    const float* b1_rel  = (const float*)d_in[6];
    const float* w1_root = (const float*)d_in[7];
    const float* w2_rel  = (const float*)d_in[8];
    const float* b2_rel  = (const float*)d_in[9];
    const float* w2_root = (const float*)d_in[10];
    const float* cls1_w  = (const float*)d_in[11];
    const float* cls1_b  = (const float*)d_in[12];
    const float* cls2_w  = (const float*)d_in[13];
    const float* cls2_b  = (const float*)d_in[14];
    float* out = (float*)d_out;

    unsigned *p_hb, *p_aggb;
    __nv_bfloat16 *p_b1hi, *p_b1lo, *p_b2hi, *p_b2lo;
    cudaGetSymbolAddress((void**)&p_hb,   g_hb);
    cudaGetSymbolAddress((void**)&p_aggb, g_aggb);
    cudaGetSymbolAddress((void**)&p_b1hi, g_b1hi);
    cudaGetSymbolAddress((void**)&p_b1lo, g_b1lo);
    cudaGetSymbolAddress((void**)&p_b2hi, g_b2hi);
    cudaGetSymbolAddress((void**)&p_b2lo, g_b2lo);

    static cudaStream_t s2 = nullptr;
    static cudaEvent_t evFork = nullptr, evJoin = nullptr;
    static int smem_set = 0;
    if (!smem_set) {
        cudaFuncSetAttribute(linear_bf16_kernel<0>,
                             cudaFuncAttributeMaxDynamicSharedMemorySize,
                             GEMM_SMEM_BYTES);
        cudaFuncSetAttribute(linear_bf16_kernel<1>,
                             cudaFuncAttributeMaxDynamicSharedMemorySize,
                             GEMM_SMEM_BYTES);
        cudaStreamCreateWithFlags(&s2, cudaStreamNonBlocking);
        cudaEventCreateWithFlags(&evFork, cudaEventDisableTiming);
        cudaEventCreateWithFlags(&evJoin, cudaEventDisableTiming);
        smem_set = 1;
    }

    // ---- fork: CSR build on side stream, embedding path on main stream ----
    cudaEventRecord(evFork, 0);
    cudaStreamWaitEvent(s2, evFork, 0);

    zero_deg_kernel<<<(N_NODES + 255) / 256, 256, 0, s2>>>();
    hist_kernel<<<(N_EDGES / 4 + 255) / 256, 256, 0, s2>>>(eidx);
    scanA_kernel<<<SCB, 256, 0, s2>>>();
    scanB_kernel<<<1, 256, 0, s2>>>();
    scanC_kernel<<<SCB, 256, 0, s2>>>();
    reorder_kernel<<<(N_EDGES / 4 + 255) / 256, 256, 0, s2>>>(eidx, eweight);
    cudaEventRecord(evJoin, s2);

    prep_weights_kernel<<<64, 256>>>(w1_rel, w1_root, w2_rel, w2_root);
    zero_pool_kernel<<<(N_GRAPHS * HIDDEN + 255) / 256, 256>>>();
    embed_kernel<<<(N_NODES + 7) / 8, 256>>>(x, emb_w);

    cudaStreamWaitEvent(0, evJoin, 0);

    int nTiles = (N_NODES + 127) / 128;
    // layer 1: out -> g_hb (bf16)
    agg_csr_kernel<<<(N_NODES * 32 + 255) / 256, 256>>>();
    linear_bf16_kernel<0><<<nTiles * 2, 256, GEMM_SMEM_BYTES>>>(
        p_aggb, p_hb, p_b1hi, p_b1lo, b1_rel, p_hb, nullptr);
    // layer 2: fused fp32 pooling
    agg_csr_kernel<<<(N_NODES * 32 + 255) / 256, 256>>>();
    linear_bf16_kernel<1><<<nTiles * 2, 256, GEMM_SMEM_BYTES>>>(
        p_aggb, p_hb, p_b2hi, p_b2lo, b2_rel, nullptr, batch);

    classifier_kernel<<<32, 256>>>(cls1_w, cls1_b, cls2_w, cls2_b, out);
}